// round 1
// baseline (speedup 1.0000x reference)
#include <cuda_runtime.h>
#include <cstdint>

#define SEQ    512
#define BATCH  512
#define IN_DIM 128
#define NQ     8
#define D_TOT  136   // IN_DIM + NQ

// Scratch: Zx[s][b][q][g]  (g fastest so each lane q reads a float4 of 4 gates)
__device__ float g_zx[(size_t)SEQ * BATCH * 32];

typedef unsigned long long ull;

// --- packed fp32x2 FMA (Blackwell; PTX-only, ptxas never auto-fuses) ---
__device__ __forceinline__ ull fma2(ull a, ull b, ull c) {
    ull d;
    asm("fma.rn.f32x2 %0, %1, %2, %3;" : "=l"(d) : "l"(a), "l"(b), "l"(c));
    return d;
}
__device__ __forceinline__ ull dup2(float x) {
    ull d;
    unsigned u = __float_as_uint(x);
    asm("mov.b64 %0, {%1, %1};" : "=l"(d) : "r"(u));
    return d;
}

__device__ __forceinline__ float sigmoidf_fast(float x) {
    return __fdividef(1.0f, 1.0f + __expf(-x));
}
__device__ __forceinline__ float tanhf_fast(float x) {
    // tanh(x) = 2*sigmoid(2x) - 1
    return fmaf(2.0f, sigmoidf_fast(2.0f * x), -1.0f);
}

// ============================================================================
// Kernel 1: Zx[row][o] = sum_d x[row][d] * W[g][q][d]  + b[g][q] + qp[g][q]
//   row = s*BATCH + b,  o = q*4 + g  (g fastest)
//   Thread-per-row; W broadcast from shared (LDS.128, all lanes same address);
//   accumulators packed as f32x2 pairs.
// ============================================================================
__global__ __launch_bounds__(256) void zx_kernel(
    const float* __restrict__ x, const float* __restrict__ W,
    const float* __restrict__ b, const float* __restrict__ qp)
{
    // Ws[d][pair j] : ulonglong2 = outputs {4j, 4j+1, 4j+2, 4j+3} packed as 2x f32x2
    __shared__ ulonglong2 Ws[IN_DIM * 4];   // 128 * 4 * 16B = 8KB... (4 pairs of ull2 = 16 floats? no: 4*ull2 = 8 ull = 16 floats) -> need 8 ull2 per d
    __shared__ ulonglong2 Ws_hi[IN_DIM * 4];
    __shared__ float bias[32];

    int tid = threadIdx.x;
    // Stage W transposed: element o of row d  (o = q*4+g)
    float* WsF   = (float*)Ws;     // holds outputs 0..15 of each d
    float* WsFhi = (float*)Ws_hi;  // holds outputs 16..31 of each d
    for (int i = tid; i < IN_DIM * 32; i += 256) {
        int d = i >> 5, o = i & 31;
        int g = o & 3, q = o >> 2;
        float w = W[(g * NQ + q) * D_TOT + d];
        if (o < 16) WsF[d * 16 + o] = w;
        else        WsFhi[d * 16 + (o - 16)] = w;
    }
    if (tid < 32) {
        int g = tid & 3, q = tid >> 2;
        bias[tid] = b[g * NQ + q] + qp[g * NQ + q];
    }
    __syncthreads();

    int row = blockIdx.x * 256 + tid;                 // exact grid: no bounds check
    const float4* xr = (const float4*)(x + (size_t)row * IN_DIM);

    ull acc[16];
#pragma unroll
    for (int i = 0; i < 16; i++) acc[i] = 0ULL;

#pragma unroll 4
    for (int d4 = 0; d4 < IN_DIM / 4; d4++) {
        float4 xv = xr[d4];
        float xs[4] = {xv.x, xv.y, xv.z, xv.w};
#pragma unroll
        for (int k = 0; k < 4; k++) {
            int d = d4 * 4 + k;
            ull xdd = dup2(xs[k]);
            const ulonglong2* wlo = Ws    + d * 4;
            const ulonglong2* whi = Ws_hi + d * 4;
#pragma unroll
            for (int j = 0; j < 4; j++) {
                ulonglong2 wp = wlo[j];
                acc[2 * j]     = fma2(xdd, wp.x, acc[2 * j]);
                acc[2 * j + 1] = fma2(xdd, wp.y, acc[2 * j + 1]);
            }
#pragma unroll
            for (int j = 0; j < 4; j++) {
                ulonglong2 wp = whi[j];
                acc[8 + 2 * j]     = fma2(xdd, wp.x, acc[8 + 2 * j]);
                acc[8 + 2 * j + 1] = fma2(xdd, wp.y, acc[8 + 2 * j + 1]);
            }
        }
    }

    float outv[32];
#pragma unroll
    for (int j = 0; j < 16; j++) {
        outv[2 * j]     = __uint_as_float((unsigned)(acc[j] & 0xffffffffu)) + bias[2 * j];
        outv[2 * j + 1] = __uint_as_float((unsigned)(acc[j] >> 32))         + bias[2 * j + 1];
    }
    float4* zr = (float4*)(g_zx + (size_t)row * 32);
#pragma unroll
    for (int j = 0; j < 8; j++)
        zr[j] = make_float4(outv[4 * j], outv[4 * j + 1], outv[4 * j + 2], outv[4 * j + 3]);
}

// ============================================================================
// Kernel 2: sequential recurrence. 8 lanes per batch element (lane = q),
// 4 batch elements per warp, 1 warp per block, 128 blocks.
//   Each lane handles all 4 gates for its q: z -> cos -> width-8 cumprod scan
//   (cross-lane shfl) -> gates local -> c,h update -> h broadcast via shfl.
// ============================================================================
__global__ __launch_bounds__(32) void rnn_kernel(
    const float* __restrict__ W, const float* __restrict__ h0,
    const float* __restrict__ c0, float* __restrict__ out)
{
    int lane = threadIdx.x;
    int gi = lane >> 3;                  // group within warp: 0..3
    int q  = lane & 7;
    int bb = blockIdx.x * 4 + gi;        // batch index 0..511

    // Recurrent weights for this q, all 4 gates (columns 128..135 of W)
    float Wh[4][8];
#pragma unroll
    for (int g = 0; g < 4; g++)
#pragma unroll
        for (int j = 0; j < 8; j++)
            Wh[g][j] = W[(g * NQ + q) * D_TOT + IN_DIM + j];

    float h[8];
#pragma unroll
    for (int j = 0; j < 8; j++) h[j] = h0[bb * 8 + j];
    float c = c0[bb * 8 + q];

    const float4* zx = (const float4*)g_zx;
    const size_t lane_idx = (size_t)bb * 8 + q;        // within one timestep
    const size_t step_stride = (size_t)BATCH * 8;      // float4 per step

    float4 zc = zx[lane_idx];                          // s = 0 (prefetched)

    for (int s = 0; s < SEQ; s++) {
        // Prefetch next step's Zx (h-independent, overlaps the chain below)
        int sn = (s + 1 < SEQ) ? (s + 1) : s;
        float4 zn = zx[(size_t)sn * step_stride + lane_idx];

        // z_g = Zx_g + h . Wh[g]   (h replicated locally -> no shfl in dot)
        float p0 = zc.x, p1 = zc.y, p2 = zc.z, p3 = zc.w;
#pragma unroll
        for (int j = 0; j < 8; j++) {
            p0 = fmaf(h[j], Wh[0][j], p0);
            p1 = fmaf(h[j], Wh[1][j], p1);
            p2 = fmaf(h[j], Wh[2][j], p2);
            p3 = fmaf(h[j], Wh[3][j], p3);
        }

        p0 = __cosf(p0); p1 = __cosf(p1); p2 = __cosf(p2); p3 = __cosf(p3);

        // Inclusive cumprod over q within each 8-lane segment (3 shfl levels)
#pragma unroll
        for (int off = 1; off < 8; off <<= 1) {
            float t0 = __shfl_up_sync(0xffffffffu, p0, off, 8);
            float t1 = __shfl_up_sync(0xffffffffu, p1, off, 8);
            float t2 = __shfl_up_sync(0xffffffffu, p2, off, 8);
            float t3 = __shfl_up_sync(0xffffffffu, p3, off, 8);
            if (q >= off) { p0 *= t0; p1 *= t1; p2 *= t2; p3 *= t3; }
        }

        // gates (order: forget, input, update, output)
        float f  = sigmoidf_fast(p0);
        float i  = sigmoidf_fast(p1);
        float gg = tanhf_fast(p2);
        float o  = sigmoidf_fast(p3);

        c = fmaf(f, c, i * gg);
        float hq = o * tanhf_fast(c);

        out[((size_t)s * BATCH + bb) * 8 + q] = hq;

        // Broadcast new h across the 8-lane segment for the next dot
#pragma unroll
        for (int j = 0; j < 8; j++)
            h[j] = __shfl_sync(0xffffffffu, hq, j, 8);

        zc = zn;
    }

    // Final states: h_f then c_f after the outputs block
    size_t base = (size_t)SEQ * BATCH * 8;
    out[base + (size_t)bb * 8 + q]                     = h[q];
    out[base + (size_t)BATCH * 8 + (size_t)bb * 8 + q] = c;
}

extern "C" void kernel_launch(void* const* d_in, const int* in_sizes, int n_in,
                              void* d_out, int out_size) {
    const float* x  = (const float*)d_in[0];   // inputs (512,512,128)
    const float* h0 = (const float*)d_in[1];   // (512,8)
    const float* c0 = (const float*)d_in[2];   // (512,8)
    const float* W  = (const float*)d_in[3];   // (4,8,136)
    const float* b  = (const float*)d_in[4];   // (4,8)
    const float* qp = (const float*)d_in[5];   // (4,8)
    float* out = (float*)d_out;

    zx_kernel<<<(SEQ * BATCH) / 256, 256>>>(x, W, b, qp);
    rnn_kernel<<<BATCH / 4, 32>>>(W, h0, c0, out);
}

// round 2
// speedup vs baseline: 1.0804x; 1.0804x over previous
#include <cuda_runtime.h>
#include <cstdint>

#define SEQ    512
#define BATCH  512
#define IN_DIM 128
#define NQ     8
#define D_TOT  136   // IN_DIM + NQ

// Scratch: Zx[s][b][o], o = g*8 + q  (o == lane in rnn kernel, == W row index)
__device__ float g_zx[(size_t)SEQ * BATCH * 32];

typedef unsigned long long ull;

// --- packed fp32x2 FMA (Blackwell; PTX-only, ptxas never auto-fuses) ---
__device__ __forceinline__ ull fma2(ull a, ull b, ull c) {
    ull d;
    asm("fma.rn.f32x2 %0, %1, %2, %3;" : "=l"(d) : "l"(a), "l"(b), "l"(c));
    return d;
}
__device__ __forceinline__ ull dup2(float x) {
    ull d;
    unsigned u = __float_as_uint(x);
    asm("mov.b64 %0, {%1, %1};" : "=l"(d) : "r"(u));
    return d;
}

// Padé [7/6] tanh: exact to ~1e-7 for |x| <= 2.1, ~1e-12 for |x| <= 1.
// tanh(x) = x(135135 + 17325 t + 378 t^2 + t^3) / (135135 + 62370 t + 3150 t^2 + 28 t^3)
__device__ __forceinline__ float tanh_pade(float x) {
    float t = x * x;
    float A = t + 378.0f;
    A = fmaf(A, t, 17325.0f);
    A = fmaf(A, t, 135135.0f);
    float B = fmaf(28.0f, t, 3150.0f);
    B = fmaf(B, t, 62370.0f);
    B = fmaf(B, t, 135135.0f);
    return __fdividef(x * A, B);
}

// ============================================================================
// Kernel 1: Zx[row][o] = sum_d x[row][d] * W[o][d]  + b[o] + qp[o]
//   row = s*BATCH + b,  o = g*8 + q == W row index (W is (4,8,136) contiguous)
//   Thread-per-row; W broadcast from shared; acc packed as f32x2 pairs.
// ============================================================================
__global__ __launch_bounds__(256) void zx_kernel(
    const float* __restrict__ x, const float* __restrict__ W,
    const float* __restrict__ b, const float* __restrict__ qp)
{
    __shared__ ulonglong2 Ws[IN_DIM * 4];     // outputs 0..15 of each d
    __shared__ ulonglong2 Ws_hi[IN_DIM * 4];  // outputs 16..31 of each d
    __shared__ float bias[32];

    int tid = threadIdx.x;
    float* WsF   = (float*)Ws;
    float* WsFhi = (float*)Ws_hi;
    for (int i = tid; i < IN_DIM * 32; i += 256) {
        int d = i >> 5, o = i & 31;
        float w = W[o * D_TOT + d];          // row o = g*8+q directly
        if (o < 16) WsF[d * 16 + o] = w;
        else        WsFhi[d * 16 + (o - 16)] = w;
    }
    if (tid < 32) bias[tid] = b[tid] + qp[tid];
    __syncthreads();

    int row = blockIdx.x * 256 + tid;
    const float4* xr = (const float4*)(x + (size_t)row * IN_DIM);

    ull acc[16];
#pragma unroll
    for (int i = 0; i < 16; i++) acc[i] = 0ULL;

#pragma unroll 4
    for (int d4 = 0; d4 < IN_DIM / 4; d4++) {
        float4 xv = xr[d4];
        float xs[4] = {xv.x, xv.y, xv.z, xv.w};
#pragma unroll
        for (int k = 0; k < 4; k++) {
            int d = d4 * 4 + k;
            ull xdd = dup2(xs[k]);
            const ulonglong2* wlo = Ws    + d * 4;
            const ulonglong2* whi = Ws_hi + d * 4;
#pragma unroll
            for (int j = 0; j < 4; j++) {
                ulonglong2 wp = wlo[j];
                acc[2 * j]     = fma2(xdd, wp.x, acc[2 * j]);
                acc[2 * j + 1] = fma2(xdd, wp.y, acc[2 * j + 1]);
            }
#pragma unroll
            for (int j = 0; j < 4; j++) {
                ulonglong2 wp = whi[j];
                acc[8 + 2 * j]     = fma2(xdd, wp.x, acc[8 + 2 * j]);
                acc[8 + 2 * j + 1] = fma2(xdd, wp.y, acc[8 + 2 * j + 1]);
            }
        }
    }

    float outv[32];
#pragma unroll
    for (int j = 0; j < 16; j++) {
        outv[2 * j]     = __uint_as_float((unsigned)(acc[j] & 0xffffffffu)) + bias[2 * j];
        outv[2 * j + 1] = __uint_as_float((unsigned)(acc[j] >> 32))         + bias[2 * j + 1];
    }
    float4* zr = (float4*)(g_zx + (size_t)row * 32);
#pragma unroll
    for (int j = 0; j < 8; j++)
        zr[j] = make_float4(outv[4 * j], outv[4 * j + 1], outv[4 * j + 2], outv[4 * j + 3]);
}

// ============================================================================
// Kernel 2: recurrence. ONE WARP PER BATCH ELEMENT. lane = g*8 + q.
//   Each lane: 1 dot (8 FMA), 1 cos, cumprod via all-gather + masked tree,
//   uniform Padé-tanh gate (f/i/o: 0.5+0.5*tanh(x/2); g: tanh(x)),
//   gate gather via 4 idx-shfls (c replicated per lane for q=lane&7),
//   Padé tanh(c), h broadcast via 8 shfls.
// ============================================================================
__global__ __launch_bounds__(128) void rnn_kernel(
    const float* __restrict__ W, const float* __restrict__ h0,
    const float* __restrict__ c0, float* __restrict__ out)
{
    const unsigned FULL = 0xffffffffu;
    int lane = threadIdx.x & 31;
    int warp = threadIdx.x >> 5;
    int bb   = blockIdx.x * 4 + warp;    // batch 0..511
    int q    = lane & 7;
    int g    = lane >> 3;

    // Recurrent weights: W row index = lane (= g*8+q), cols 128..135
    float Wh[8];
#pragma unroll
    for (int j = 0; j < 8; j++) Wh[j] = W[lane * D_TOT + IN_DIM + j];

    float h[8];
#pragma unroll
    for (int j = 0; j < 8; j++) h[j] = h0[bb * 8 + j];
    float c = c0[bb * 8 + q];            // replicated across the 4 gate groups

    // loop-invariant lane constants
    bool inc[8];
#pragma unroll
    for (int j = 0; j < 8; j++) inc[j] = (j <= q);
    const float asc   = (g == 2) ? 1.0f : 0.5f;  // arg scale AND output scale
    const float obias = (g == 2) ? 0.0f : 0.5f;
    const bool  do_store = (lane < 8);

    const float* zp = g_zx + (size_t)bb * 32 + lane;
    const int STRIDE = BATCH * 32;       // floats per timestep

    float zc = zp[0];
    float zn = zp[STRIDE];               // SEQ >= 2 always here

    for (int s = 0; s < SEQ; s++) {
        int s2 = s + 2 < SEQ ? s + 2 : SEQ - 1;
        float znn = zp[(size_t)s2 * STRIDE];

        // z = zx + h . Wh   (two parallel FMA chains)
        float a0 = zc, a1 = 0.0f;
#pragma unroll
        for (int j = 0; j < 8; j += 2) {
            a0 = fmaf(h[j],     Wh[j],     a0);
            a1 = fmaf(h[j + 1], Wh[j + 1], a1);
        }
        float p = __cosf(a0 + a1);

        // cumprod over q within the 8-lane gate group: all-gather + masked tree
        float cj[8];
#pragma unroll
        for (int j = 0; j < 8; j++) cj[j] = __shfl_sync(FULL, p, j, 8);
#pragma unroll
        for (int j = 1; j < 8; j++) cj[j] = inc[j] ? cj[j] : 1.0f;
        float r01 = cj[0] * cj[1], r23 = cj[2] * cj[3];
        float r45 = cj[4] * cj[5], r67 = cj[6] * cj[7];
        float prod = (r01 * r23) * (r45 * r67);

        // uniform gate: v = obias + asc * tanh(asc * prod)
        float r = tanh_pade(asc * prod);
        float v = fmaf(asc, r, obias);

        // gather f,i,g,o for this lane's q
        float fv = __shfl_sync(FULL, v, q);
        float iv = __shfl_sync(FULL, v, 8 + q);
        float gv = __shfl_sync(FULL, v, 16 + q);
        float ov = __shfl_sync(FULL, v, 24 + q);

        c = fmaf(fv, c, iv * gv);
        float hq = ov * tanh_pade(c);

        if (do_store)
            out[((size_t)s * BATCH + bb) * 8 + lane] = hq;

        // broadcast new h (lane j holds h_j for j<8)
#pragma unroll
        for (int j = 0; j < 8; j++) h[j] = __shfl_sync(FULL, hq, j);

        zc = zn;
        zn = znn;
    }

    // Final states: h_f then c_f after the outputs block
    size_t base = (size_t)SEQ * BATCH * 8;
    if (do_store) {
        out[base + (size_t)bb * 8 + lane]                  = h[lane];
        out[base + (size_t)BATCH * 8 + (size_t)bb * 8 + q] = c;
    }
}

extern "C" void kernel_launch(void* const* d_in, const int* in_sizes, int n_in,
                              void* d_out, int out_size) {
    const float* x  = (const float*)d_in[0];   // inputs (512,512,128)
    const float* h0 = (const float*)d_in[1];   // (512,8)
    const float* c0 = (const float*)d_in[2];   // (512,8)
    const float* W  = (const float*)d_in[3];   // (4,8,136)
    const float* b  = (const float*)d_in[4];   // (4,8)
    const float* qp = (const float*)d_in[5];   // (4,8)
    float* out = (float*)d_out;

    zx_kernel<<<(SEQ * BATCH) / 256, 256>>>(x, W, b, qp);
    rnn_kernel<<<BATCH / 4, 128>>>(W, h0, c0, out);
}

// round 3
// speedup vs baseline: 1.1355x; 1.0511x over previous
#include <cuda_runtime.h>
#include <cstdint>

#define SEQ    512
#define BATCH  512
#define IN_DIM 128
#define NQ     8
#define D_TOT  136   // IN_DIM + NQ

// Scratch: Zx[s][b][o], o = g*8 + q  (o == lane in rnn kernel, == W row index)
__device__ float g_zx[(size_t)SEQ * BATCH * 32];

typedef unsigned long long ull;

// --- packed fp32x2 FMA (Blackwell; PTX-only, ptxas never auto-fuses) ---
__device__ __forceinline__ ull fma2(ull a, ull b, ull c) {
    ull d;
    asm("fma.rn.f32x2 %0, %1, %2, %3;" : "=l"(d) : "l"(a), "l"(b), "l"(c));
    return d;
}
__device__ __forceinline__ ull dup2(float x) {
    ull d;
    unsigned u = __float_as_uint(x);
    asm("mov.b64 %0, {%1, %1};" : "=l"(d) : "r"(u));
    return d;
}

// Padé [5/4] tanh: err <= 2e-5 abs for |x| <= 2.1 (<= 1e-7 for |x| <= 1).
// tanh(x) ~= x (t^2 + 105 t + 945) / (15 t^2 + 420 t + 945),  t = x^2
__device__ __forceinline__ float tanh_pade(float x) {
    float t = x * x;
    float A = fmaf(t + 105.0f, t, 945.0f);
    float B = fmaf(fmaf(15.0f, t, 420.0f), t, 945.0f);
    return __fdividef(x * A, B);
}

// ============================================================================
// Kernel 1: Zx[row][o] = sum_d x[row][d] * W[o][d]  + b[o] + qp[o]
// ============================================================================
__global__ __launch_bounds__(256) void zx_kernel(
    const float* __restrict__ x, const float* __restrict__ W,
    const float* __restrict__ b, const float* __restrict__ qp)
{
    __shared__ ulonglong2 Ws[IN_DIM * 4];     // outputs 0..15 of each d
    __shared__ ulonglong2 Ws_hi[IN_DIM * 4];  // outputs 16..31 of each d
    __shared__ float bias[32];

    int tid = threadIdx.x;
    float* WsF   = (float*)Ws;
    float* WsFhi = (float*)Ws_hi;
    for (int i = tid; i < IN_DIM * 32; i += 256) {
        int d = i >> 5, o = i & 31;
        float w = W[o * D_TOT + d];          // row o = g*8+q directly
        if (o < 16) WsF[d * 16 + o] = w;
        else        WsFhi[d * 16 + (o - 16)] = w;
    }
    if (tid < 32) bias[tid] = b[tid] + qp[tid];
    __syncthreads();

    int row = blockIdx.x * 256 + tid;
    const float4* xr = (const float4*)(x + (size_t)row * IN_DIM);

    ull acc[16];
#pragma unroll
    for (int i = 0; i < 16; i++) acc[i] = 0ULL;

#pragma unroll 4
    for (int d4 = 0; d4 < IN_DIM / 4; d4++) {
        float4 xv = xr[d4];
        float xs[4] = {xv.x, xv.y, xv.z, xv.w};
#pragma unroll
        for (int k = 0; k < 4; k++) {
            int d = d4 * 4 + k;
            ull xdd = dup2(xs[k]);
            const ulonglong2* wlo = Ws    + d * 4;
            const ulonglong2* whi = Ws_hi + d * 4;
#pragma unroll
            for (int j = 0; j < 4; j++) {
                ulonglong2 wp = wlo[j];
                acc[2 * j]     = fma2(xdd, wp.x, acc[2 * j]);
                acc[2 * j + 1] = fma2(xdd, wp.y, acc[2 * j + 1]);
            }
#pragma unroll
            for (int j = 0; j < 4; j++) {
                ulonglong2 wp = whi[j];
                acc[8 + 2 * j]     = fma2(xdd, wp.x, acc[8 + 2 * j]);
                acc[8 + 2 * j + 1] = fma2(xdd, wp.y, acc[8 + 2 * j + 1]);
            }
        }
    }

    float outv[32];
#pragma unroll
    for (int j = 0; j < 16; j++) {
        outv[2 * j]     = __uint_as_float((unsigned)(acc[j] & 0xffffffffu)) + bias[2 * j];
        outv[2 * j + 1] = __uint_as_float((unsigned)(acc[j] >> 32))         + bias[2 * j + 1];
    }
    float4* zr = (float4*)(g_zx + (size_t)row * 32);
#pragma unroll
    for (int j = 0; j < 8; j++)
        zr[j] = make_float4(outv[4 * j], outv[4 * j + 1], outv[4 * j + 2], outv[4 * j + 3]);
}

// ============================================================================
// Kernel 2: recurrence. ONE WARP PER BATCH ELEMENT. lane = g*8 + q.
//   zx prefetched 4 steps deep (rotating reg buffer, unroll-4) to hide DRAM.
// ============================================================================
__global__ __launch_bounds__(128) void rnn_kernel(
    const float* __restrict__ W, const float* __restrict__ h0,
    const float* __restrict__ c0, float* __restrict__ out)
{
    const unsigned FULL = 0xffffffffu;
    int lane = threadIdx.x & 31;
    int warp = threadIdx.x >> 5;
    int bb   = blockIdx.x * 4 + warp;    // batch 0..511
    int q    = lane & 7;
    int g    = lane >> 3;

    // Recurrent weights: W row index = lane (= g*8+q), cols 128..135
    float Wh[8];
#pragma unroll
    for (int j = 0; j < 8; j++) Wh[j] = W[lane * D_TOT + IN_DIM + j];

    float h[8];
#pragma unroll
    for (int j = 0; j < 8; j++) h[j] = h0[bb * 8 + j];
    float c = c0[bb * 8 + q];            // replicated across the 4 gate groups

    // loop-invariant lane constants
    bool inc[8];
#pragma unroll
    for (int j = 0; j < 8; j++) inc[j] = (j <= q);
    const float asc   = (g == 2) ? 1.0f : 0.5f;  // arg scale AND output scale
    const float obias = (g == 2) ? 0.0f : 0.5f;
    const bool  do_store = (lane < 8);

    const float* zp = g_zx + (size_t)bb * 32 + lane;
    const int STRIDE = BATCH * 32;               // floats per timestep

    // 4-deep prefetch buffer (SEQ >= 8)
    float zbuf[4];
#pragma unroll
    for (int u = 0; u < 4; u++) zbuf[u] = zp[(size_t)u * STRIDE];

    float* op = out + (size_t)bb * 8 + lane;     // lanes 0-7 store
    const size_t OSTRIDE = (size_t)BATCH * 8;

    for (int s = 0; s < SEQ; s += 4) {
#pragma unroll
        for (int u = 0; u < 4; u++) {
            // prefetch step s+u+4 (clamped; duplicate loads at tail are harmless)
            int sp = s + u + 4; sp = sp < SEQ ? sp : SEQ - 1;
            float znew = zp[(size_t)sp * STRIDE];

            // z = zx + h . Wh   (two parallel FMA chains)
            float a0 = zbuf[u], a1 = 0.0f;
#pragma unroll
            for (int j = 0; j < 8; j += 2) {
                a0 = fmaf(h[j],     Wh[j],     a0);
                a1 = fmaf(h[j + 1], Wh[j + 1], a1);
            }
            float p = __cosf(a0 + a1);

            // cumprod over q within the 8-lane gate group: all-gather + masked tree
            float cj[8];
#pragma unroll
            for (int j = 0; j < 8; j++) cj[j] = __shfl_sync(FULL, p, j, 8);
#pragma unroll
            for (int j = 1; j < 8; j++) cj[j] = inc[j] ? cj[j] : 1.0f;
            float r01 = cj[0] * cj[1], r23 = cj[2] * cj[3];
            float r45 = cj[4] * cj[5], r67 = cj[6] * cj[7];
            float prod = (r01 * r23) * (r45 * r67);

            // uniform gate: v = obias + asc * tanh(asc * prod)
            float r = tanh_pade(asc * prod);
            float v = fmaf(asc, r, obias);

            // gather f,i,g,o for this lane's q
            float fv = __shfl_sync(FULL, v, q);
            float iv = __shfl_sync(FULL, v, 8 + q);
            float gv = __shfl_sync(FULL, v, 16 + q);
            float ov = __shfl_sync(FULL, v, 24 + q);

            c = fmaf(fv, c, iv * gv);
            float hq = ov * tanh_pade(c);

            if (do_store) *op = hq;
            op += OSTRIDE;

            // broadcast new h (lane j holds hq for q=j in group 0..3)
#pragma unroll
            for (int j = 0; j < 8; j++) h[j] = __shfl_sync(FULL, hq, j, 8);

            zbuf[u] = znew;
        }
    }

    // Final states: h_f then c_f after the outputs block
    size_t base = (size_t)SEQ * BATCH * 8;
    if (do_store) {
        out[base + (size_t)bb * 8 + lane]                  = h[lane];
        out[base + (size_t)BATCH * 8 + (size_t)bb * 8 + q] = c;
    }
}

extern "C" void kernel_launch(void* const* d_in, const int* in_sizes, int n_in,
                              void* d_out, int out_size) {
    const float* x  = (const float*)d_in[0];   // inputs (512,512,128)
    const float* h0 = (const float*)d_in[1];   // (512,8)
    const float* c0 = (const float*)d_in[2];   // (512,8)
    const float* W  = (const float*)d_in[3];   // (4,8,136)
    const float* b  = (const float*)d_in[4];   // (4,8)
    const float* qp = (const float*)d_in[5];   // (4,8)
    float* out = (float*)d_out;

    zx_kernel<<<(SEQ * BATCH) / 256, 256>>>(x, W, b, qp);
    rnn_kernel<<<BATCH / 4, 128>>>(W, h0, c0, out);
}